// round 6
// baseline (speedup 1.0000x reference)
#include <cuda_runtime.h>
#include <cuda_bf16.h>
#include <cstdint>

// Problem constants
#define PB 4
#define PS 2048
#define PD 1024
#define PC 32
#define PNL 256
#define PH 16
#define PDK 64
#define PCHUNK 64
#define PSCALE 0.125f
#define VALID_ROWS 1985

// -------------------- scratch --------------------
__device__ __nv_bfloat16 g_X [PB*PS*PD];
__device__ __nv_bfloat16 g_E [PB*PC*PNL*PD];
__device__ __nv_bfloat16 g_AO[PB*PS*PD];
__device__ __nv_bfloat16 g_Wt[4*PD*PD];
__device__ float g_Q [PB*PS*PD];
__device__ float g_K [PB*PC*PNL*PD];
__device__ float g_V [PB*PC*PNL*PD];

// -------------------- helpers --------------------
__device__ __forceinline__ uint32_t f2tf32(float f){
    uint32_t r; asm("cvt.rna.tf32.f32 %0, %1;" : "=r"(r) : "f"(f)); return r;
}
__device__ __forceinline__ void mma_tf32(float c[4], uint32_t a0, uint32_t a1, uint32_t a2,
                                         uint32_t a3, uint32_t b0, uint32_t b1){
    asm volatile("mma.sync.aligned.m16n8k8.row.col.f32.tf32.tf32.f32 "
        "{%0,%1,%2,%3},{%4,%5,%6,%7},{%8,%9},{%0,%1,%2,%3};\n"
        : "+f"(c[0]),"+f"(c[1]),"+f"(c[2]),"+f"(c[3])
        : "r"(a0),"r"(a1),"r"(a2),"r"(a3),"r"(b0),"r"(b1));
}
__device__ __forceinline__ void mma_bf16(float c[4], uint32_t a0, uint32_t a1, uint32_t a2,
                                         uint32_t a3, uint32_t b0, uint32_t b1){
    asm volatile("mma.sync.aligned.m16n8k16.row.col.f32.bf16.bf16.f32 "
        "{%0,%1,%2,%3},{%4,%5,%6,%7},{%8,%9},{%0,%1,%2,%3};\n"
        : "+f"(c[0]),"+f"(c[1]),"+f"(c[2]),"+f"(c[3])
        : "r"(a0),"r"(a1),"r"(a2),"r"(a3),"r"(b0),"r"(b1));
}
__device__ __forceinline__ void cp16(uint32_t s, const void* g){
    asm volatile("cp.async.cg.shared.global [%0], [%1], 16;" :: "r"(s), "l"(g));
}
__device__ __forceinline__ uint32_t smem_u32(const void* p){
    uint32_t a;
    asm("{ .reg .u64 t; cvta.to.shared.u64 t, %1; cvt.u32.u64 %0, t; }" : "=r"(a) : "l"(p));
    return a;
}
__device__ __forceinline__ uint32_t lds32(const char* smbase, uint32_t off){
    return *(const uint32_t*)(smbase + off);
}

// -------------------- bf16 GEMM --------------------
// C(M,1024) = A(M,1024) @ Wt^T + bias. A, Wt bf16 row-major [row][K].
// CTA tile 128x256, k-tile 64 (128B rows), 3-stage cp.async.
// 8 warps as 2m x 4n, warp tile 64x64 (4 m-tiles x 8 n-tiles).
// smem/stage: A 16KB + B 32KB = 48KB; 3 stages = 144KB; 1 CTA/SM.
#define NS 16
#define STG (16384 + 32768)
#define G_SMEM (3*STG)

template<int EPI>
__global__ void __launch_bounds__(256, 1) gemm_bf16_kernel(
    const __nv_bfloat16* __restrict__ A, const __nv_bfloat16* __restrict__ Bt,
    const float* __restrict__ bias, float* __restrict__ Cout,
    const float* __restrict__ resid)
{
    extern __shared__ char smc[];
    const uint32_t smem_base = smem_u32(smc);
    const int tid = threadIdx.x;
    const int wid = tid >> 5, lane = tid & 31;
    const int wm = wid & 1, wn = wid >> 1;       // 2m x 4n
    const int quad = lane >> 2, qt = lane & 3;
    const int bm = blockIdx.y, bn = blockIdx.x;
    const long arow0 = (long)bm * 128;
    const long brow0 = (long)bn * 256;

    float acc[4][8][4] = {};

    auto load_stage = [&](int kt, int s){
        const uint32_t sb = smem_base + s*STG;
#pragma unroll
        for (int i = 0; i < 4; i++){
            const int idx = i*256 + tid;
            const int r = idx >> 3, c = idx & 7;
            const int sc = c ^ (r & 7);
            cp16(sb + r*128 + sc*16, &A[(arow0 + r)*1024 + kt*64 + c*8]);
        }
#pragma unroll
        for (int i = 0; i < 8; i++){
            const int idx = i*256 + tid;
            const int r = idx >> 3, c = idx & 7;
            const int sc = c ^ (r & 7);
            cp16(sb + 16384 + r*128 + sc*16, &Bt[(brow0 + r)*1024 + kt*64 + c*8]);
        }
    };

    load_stage(0, 0); asm volatile("cp.async.commit_group;" ::: "memory");
    load_stage(1, 1); asm volatile("cp.async.commit_group;" ::: "memory");

    for (int kt = 0; kt < NS; ++kt){
        if (kt < NS-1) asm volatile("cp.async.wait_group 1;" ::: "memory");
        else           asm volatile("cp.async.wait_group 0;" ::: "memory");
        __syncthreads();
        if (kt + 2 < NS){
            load_stage(kt + 2, (kt + 2) % 3);
            asm volatile("cp.async.commit_group;" ::: "memory");
        }
        const char* Asm = smc + (kt % 3)*STG;
        const char* Bsm = Asm + 16384;

#pragma unroll
        for (int g = 0; g < 4; ++g){
            uint32_t a[4][4];
#pragma unroll
            for (int mi = 0; mi < 4; ++mi){
                const int r0 = wm*64 + mi*16 + quad;
                const int r1 = r0 + 8;
                a[mi][0] = lds32(Asm, r0*128 + ((2*g  ) ^ (r0 & 7))*16 + qt*4);
                a[mi][1] = lds32(Asm, r1*128 + ((2*g  ) ^ (r1 & 7))*16 + qt*4);
                a[mi][2] = lds32(Asm, r0*128 + ((2*g+1) ^ (r0 & 7))*16 + qt*4);
                a[mi][3] = lds32(Asm, r1*128 + ((2*g+1) ^ (r1 & 7))*16 + qt*4);
            }
            uint32_t bfr[8][2];
#pragma unroll
            for (int ni = 0; ni < 8; ++ni){
                const int n = wn*64 + ni*8 + quad;
                bfr[ni][0] = lds32(Bsm, n*128 + ((2*g  ) ^ (n & 7))*16 + qt*4);
                bfr[ni][1] = lds32(Bsm, n*128 + ((2*g+1) ^ (n & 7))*16 + qt*4);
            }
#pragma unroll
            for (int mi = 0; mi < 4; ++mi)
#pragma unroll
                for (int ni = 0; ni < 8; ++ni)
                    mma_bf16(acc[mi][ni], a[mi][0], a[mi][1], a[mi][2], a[mi][3],
                             bfr[ni][0], bfr[ni][1]);
        }
        __syncthreads();
    }

    // epilogue
#pragma unroll
    for (int mi = 0; mi < 4; ++mi){
#pragma unroll
        for (int ni = 0; ni < 8; ++ni){
            const int gr0 = bm*128 + wm*64 + mi*16 + quad;
            const int gc  = bn*256 + wn*64 + ni*8 + qt*2;
            const float b0 = bias[gc], b1 = bias[gc+1];
#pragma unroll
            for (int half = 0; half < 2; ++half){
                const int gr = gr0 + half*8;
                const float v0 = acc[mi][ni][half*2+0] + b0;
                const float v1 = acc[mi][ni][half*2+1] + b1;
                if (EPI == 0){
                    Cout[(long)gr*1024 + gc]     = v0;
                    Cout[(long)gr*1024 + gc + 1] = v1;
                } else {
                    const int b = gr >> 11, r = gr & 2047;
                    if (r < VALID_ROWS){
                        const long o = ((long)b*PS + r + (PCHUNK-1))*PD + gc;
                        Cout[o]   = v0 + resid[o];
                        Cout[o+1] = v1 + resid[o+1];
                    }
                }
            }
        }
    }
}

// -------------------- e -> bf16 --------------------
__global__ void __launch_bounds__(256) convert_e_kernel(const float* __restrict__ e,
                                                        __nv_bfloat16* __restrict__ E){
    const long i4 = ((long)blockIdx.x*256 + threadIdx.x) * 4;
    float4 v = *(const float4*)&e[i4];
    __nv_bfloat162 lo = __float22bfloat162_rn(make_float2(v.x, v.y));
    __nv_bfloat162 hi = __float22bfloat162_rn(make_float2(v.z, v.w));
    *(__nv_bfloat162*)&E[i4]     = lo;
    *(__nv_bfloat162*)&E[i4 + 2] = hi;
}

// -------------------- weight transpose -> bf16 [N][K] --------------------
__global__ void __launch_bounds__(256) transpose_kernel(const float* __restrict__ src,
                                                        __nv_bfloat16* __restrict__ dst){
    __shared__ float t[32][33];
    const int tx = threadIdx.x, ty = threadIdx.y;
    int x = blockIdx.x*32 + tx;
    int y = blockIdx.y*32 + ty;
#pragma unroll
    for (int j=0;j<32;j+=8) t[ty+j][tx] = src[(long)(y+j)*1024 + x];
    __syncthreads();
    x = blockIdx.y*32 + tx;
    y = blockIdx.x*32 + ty;
#pragma unroll
    for (int j=0;j<32;j+=8)
        dst[(long)(y+j)*1024 + x] = __float2bfloat16_rn(t[tx][ty+j]);
}

// -------------------- LayerNorm (+pad), bf16 output --------------------
__global__ void __launch_bounds__(256) ln_kernel(
    const float* __restrict__ h, const float* __restrict__ gamma,
    const float* __restrict__ beta, __nv_bfloat16* __restrict__ X)
{
    const int row = blockIdx.x;
    const int b = row >> 11, r = row & 2047;
    const int tid = threadIdx.x;
    __nv_bfloat16* xo = X + (long)row * PD;
    if (r >= VALID_ROWS){
        __nv_bfloat162 z = __float22bfloat162_rn(make_float2(0.f,0.f));
        *(__nv_bfloat162*)&xo[tid*4]   = z;
        *(__nv_bfloat162*)&xo[tid*4+2] = z;
        return;
    }
    const float* hp = h + ((long)b*PS + r + (PCHUNK-1)) * PD;
    float4 v = *(const float4*)&hp[tid*4];
    float s  = v.x + v.y + v.z + v.w;
    float sq = v.x*v.x + v.y*v.y + v.z*v.z + v.w*v.w;
#pragma unroll
    for (int o=16;o;o>>=1){
        s  += __shfl_down_sync(0xffffffffu, s,  o);
        sq += __shfl_down_sync(0xffffffffu, sq, o);
    }
    __shared__ float rs_[8], rq_[8];
    __shared__ float mu_s, rstd_s;
    const int wid = tid>>5, lane = tid&31;
    if (!lane){ rs_[wid]=s; rq_[wid]=sq; }
    __syncthreads();
    if (tid==0){
        float ts=0.f, tq=0.f;
#pragma unroll
        for (int i=0;i<8;i++){ ts+=rs_[i]; tq+=rq_[i]; }
        float mu = ts * (1.0f/PD);
        float var = tq * (1.0f/PD) - mu*mu;
        mu_s = mu; rstd_s = rsqrtf(var + 1e-5f);
    }
    __syncthreads();
    const float mu = mu_s, rstd = rstd_s;
    float4 g  = *(const float4*)&gamma[tid*4];
    float4 be = *(const float4*)&beta[tid*4];
    float2 p0 = make_float2((v.x-mu)*rstd*g.x + be.x, (v.y-mu)*rstd*g.y + be.y);
    float2 p1 = make_float2((v.z-mu)*rstd*g.z + be.z, (v.w-mu)*rstd*g.w + be.w);
    *(__nv_bfloat162*)&xo[tid*4]   = __float22bfloat162_rn(p0);
    *(__nv_bfloat162*)&xo[tid*4+2] = __float22bfloat162_rn(p1);
}

// -------------------- attention (per b,c,h) --------------------
#define ATT_SMEM ((64*72*2 + 64*260) * 4)

__global__ void __launch_bounds__(128) attn_kernel(
    const float* __restrict__ Q, const float* __restrict__ Kb,
    const float* __restrict__ Vb, __nv_bfloat16* __restrict__ AO)
{
    extern __shared__ float sm[];
    float* Qs  = sm;
    float* KVs = sm + 64*72;
    float* Ss  = sm + 2*64*72;
    const int hh = blockIdx.x, c = blockIdx.y, b = blockIdx.z;
    const int tid = threadIdx.x, w = tid>>5, lane = tid&31;
    const int quad = lane>>2, qt = lane&3;
    const long qbase  = ((long)((b*PC + c)*PCHUNK))*PD + hh*PDK;
    const long kvbase = ((long)((b*PC + c)*PNL ))*PD + hh*PDK;

#pragma unroll
    for (int it=0; it<8; it++){
        int idx = tid + it*128;
        int r = idx>>4, c4 = idx&15;
        *(float4*)&Qs[r*72 + c4*4] = *(const float4*)&Q[qbase + (long)r*1024 + c4*4];
    }

    for (int jt=0; jt<4; jt++){
        __syncthreads();
#pragma unroll
        for (int it=0; it<8; it++){
            int idx = tid + it*128;
            int r = idx>>4, c4 = idx&15;
            *(float4*)&KVs[r*72 + c4*4] =
                *(const float4*)&Kb[kvbase + (long)(jt*64 + r)*1024 + c4*4];
        }
        __syncthreads();
        float acc[8][4] = {};
#pragma unroll
        for (int kk=0; kk<64; kk+=8){
            uint32_t af[4];
            const int ib = w*16;
            af[0]=f2tf32(Qs[(ib+quad  )*72 + kk+qt  ]);
            af[1]=f2tf32(Qs[(ib+quad+8)*72 + kk+qt  ]);
            af[2]=f2tf32(Qs[(ib+quad  )*72 + kk+qt+4]);
            af[3]=f2tf32(Qs[(ib+quad+8)*72 + kk+qt+4]);
#pragma unroll
            for (int ni=0; ni<8; ni++){
                uint32_t b0=f2tf32(KVs[(ni*8+quad)*72 + kk+qt  ]);
                uint32_t b1=f2tf32(KVs[(ni*8+quad)*72 + kk+qt+4]);
                mma_tf32(acc[ni], af[0],af[1],af[2],af[3], b0,b1);
            }
        }
#pragma unroll
        for (int ni=0; ni<8; ni++){
            const int i0 = w*16 + quad;
            const int j0 = jt*64 + ni*8 + qt*2;
            Ss[i0*260 + j0]       = acc[ni][0]*PSCALE;
            Ss[i0*260 + j0+1]     = acc[ni][1]*PSCALE;
            Ss[(i0+8)*260 + j0]   = acc[ni][2]*PSCALE;
            Ss[(i0+8)*260 + j0+1] = acc[ni][3]*PSCALE;
        }
    }
    __syncthreads();

    if (tid < 64){
        float* row = &Ss[tid*260];
        float m = -1e30f;
        for (int j=0;j<256;j++) m = fmaxf(m, row[j]);
        float ssum = 0.f;
        for (int j=0;j<256;j++){ float ev = __expf(row[j]-m); row[j]=ev; ssum+=ev; }
        const float inv = 1.0f/ssum;
        for (int j=0;j<256;j++) row[j]*=inv;
    }

    float accO[8][4] = {};
    for (int jt=0; jt<4; jt++){
        __syncthreads();
#pragma unroll
        for (int it=0; it<8; it++){
            int idx = tid + it*128;
            int r = idx>>4, c4 = idx&15;
            *(float4*)&KVs[r*72 + c4*4] =
                *(const float4*)&Vb[kvbase + (long)(jt*64 + r)*1024 + c4*4];
        }
        __syncthreads();
#pragma unroll
        for (int kk=0; kk<64; kk+=8){
            uint32_t af[4];
            const int ib = w*16;
            const int jcol = jt*64 + kk;
            af[0]=f2tf32(Ss[(ib+quad  )*260 + jcol+qt  ]);
            af[1]=f2tf32(Ss[(ib+quad+8)*260 + jcol+qt  ]);
            af[2]=f2tf32(Ss[(ib+quad  )*260 + jcol+qt+4]);
            af[3]=f2tf32(Ss[(ib+quad+8)*260 + jcol+qt+4]);
#pragma unroll
            for (int ni=0; ni<8; ni++){
                uint32_t b0=f2tf32(KVs[(kk+qt  )*72 + ni*8+quad]);
                uint32_t b1=f2tf32(KVs[(kk+qt+4)*72 + ni*8+quad]);
                mma_tf32(accO[ni], af[0],af[1],af[2],af[3], b0,b1);
            }
        }
    }
#pragma unroll
    for (int ni=0; ni<8; ni++){
        const int i0 = w*16 + quad;
        const int d0 = ni*8 + qt*2;
        *(__nv_bfloat162*)&AO[qbase + (long)i0*1024 + d0] =
            __float22bfloat162_rn(make_float2(accO[ni][0], accO[ni][1]));
        *(__nv_bfloat162*)&AO[qbase + (long)(i0+8)*1024 + d0] =
            __float22bfloat162_rn(make_float2(accO[ni][2], accO[ni][3]));
    }
}

// -------------------- copy first 63 rows --------------------
__global__ void copy_head_kernel(const float* __restrict__ h, float* __restrict__ out){
    const int idx = blockIdx.x*256 + threadIdx.x;
    if (idx >= PB*(PCHUNK-1)*(PD/4)) return;
    const int b = idx / ((PCHUNK-1)*(PD/4));
    const int rem = idx % ((PCHUNK-1)*(PD/4));
    const int s = rem >> 8, c4 = rem & 255;
    const long o = ((long)b*PS + s)*PD + c4*4;
    *(float4*)&out[o] = *(const float4*)&h[o];
}

// -------------------- launch --------------------
extern "C" void kernel_launch(void* const* d_in, const int* in_sizes, int n_in,
                              void* d_out, int out_size)
{
    const float* h     = (const float*)d_in[0];
    const float* e     = (const float*)d_in[1];
    const float* Wq    = (const float*)d_in[2];
    const float* bq    = (const float*)d_in[3];
    const float* Wk    = (const float*)d_in[4];
    const float* bk    = (const float*)d_in[5];
    const float* Wv    = (const float*)d_in[6];
    const float* bv    = (const float*)d_in[7];
    const float* Wo    = (const float*)d_in[8];
    const float* bo    = (const float*)d_in[9];
    const float* gamma = (const float*)d_in[10];
    const float* beta  = (const float*)d_in[11];
    float* out = (float*)d_out;

    void *pX,*pE,*pQ,*pK,*pV,*pA,*pW;
    cudaGetSymbolAddress(&pX, g_X);
    cudaGetSymbolAddress(&pE, g_E);
    cudaGetSymbolAddress(&pQ, g_Q);
    cudaGetSymbolAddress(&pK, g_K);
    cudaGetSymbolAddress(&pV, g_V);
    cudaGetSymbolAddress(&pA, g_AO);
    cudaGetSymbolAddress(&pW, g_Wt);
    __nv_bfloat16* Wt = (__nv_bfloat16*)pW;

    cudaFuncSetAttribute(gemm_bf16_kernel<0>, cudaFuncAttributeMaxDynamicSharedMemorySize, G_SMEM);
    cudaFuncSetAttribute(gemm_bf16_kernel<1>, cudaFuncAttributeMaxDynamicSharedMemorySize, G_SMEM);
    cudaFuncSetAttribute(attn_kernel,         cudaFuncAttributeMaxDynamicSharedMemorySize, ATT_SMEM);

    // 0) operand prep
    transpose_kernel<<<dim3(32,32), dim3(32,8)>>>(Wq, Wt + 0*PD*PD);
    transpose_kernel<<<dim3(32,32), dim3(32,8)>>>(Wk, Wt + 1*PD*PD);
    transpose_kernel<<<dim3(32,32), dim3(32,8)>>>(Wv, Wt + 2*PD*PD);
    transpose_kernel<<<dim3(32,32), dim3(32,8)>>>(Wo, Wt + 3*PD*PD);
    convert_e_kernel<<<PB*PC*PNL*PD/1024, 256>>>(e, (__nv_bfloat16*)pE);
    ln_kernel<<<PB*PS, 256>>>(h, gamma, beta, (__nv_bfloat16*)pX);
    // 1) projections (bf16 tensor cores, fp32 accum), CTA tile 128x256
    gemm_bf16_kernel<0><<<dim3(4,64),  256, G_SMEM>>>((const __nv_bfloat16*)pX, Wt + 0*PD*PD, bq, (float*)pQ, nullptr);
    gemm_bf16_kernel<0><<<dim3(4,256), 256, G_SMEM>>>((const __nv_bfloat16*)pE, Wt + 1*PD*PD, bk, (float*)pK, nullptr);
    gemm_bf16_kernel<0><<<dim3(4,256), 256, G_SMEM>>>((const __nv_bfloat16*)pE, Wt + 2*PD*PD, bv, (float*)pV, nullptr);
    // 2) attention
    attn_kernel<<<dim3(PH, PC, PB), 128, ATT_SMEM>>>((const float*)pQ, (const float*)pK,
                                                     (const float*)pV, (__nv_bfloat16*)pA);
    // 3) output projection + shifted residual
    gemm_bf16_kernel<1><<<dim3(4,64),  256, G_SMEM>>>((const __nv_bfloat16*)pA, Wt + 3*PD*PD, bo, out, h);
    // 4) head rows
    copy_head_kernel<<<(PB*(PCHUNK-1)*(PD/4) + 255)/256, 256>>>(h, out);
}

// round 7
// speedup vs baseline: 1.0659x; 1.0659x over previous
#include <cuda_runtime.h>
#include <cuda_bf16.h>
#include <cstdint>

// Problem constants
#define PB 4
#define PS 2048
#define PD 1024
#define PC 32
#define PNL 256
#define PH 16
#define PDK 64
#define PCHUNK 64
#define PSCALE 0.125f
#define VALID_ROWS 1985

// -------------------- scratch --------------------
__device__ __nv_bfloat16 g_X [PB*PS*PD];
__device__ __nv_bfloat16 g_E [PB*PC*PNL*PD];
__device__ __nv_bfloat16 g_AO[PB*PS*PD];
__device__ __nv_bfloat16 g_Wt[4*PD*PD];
__device__ float         g_Q [PB*PS*PD];
__device__ __nv_bfloat16 g_K [PB*PC*PNL*PD];
__device__ __nv_bfloat16 g_V [PB*PC*PNL*PD];

// -------------------- helpers --------------------
__device__ __forceinline__ uint32_t f2tf32(float f){
    uint32_t r; asm("cvt.rna.tf32.f32 %0, %1;" : "=r"(r) : "f"(f)); return r;
}
__device__ __forceinline__ void mma_tf32(float c[4], uint32_t a0, uint32_t a1, uint32_t a2,
                                         uint32_t a3, uint32_t b0, uint32_t b1){
    asm volatile("mma.sync.aligned.m16n8k8.row.col.f32.tf32.tf32.f32 "
        "{%0,%1,%2,%3},{%4,%5,%6,%7},{%8,%9},{%0,%1,%2,%3};\n"
        : "+f"(c[0]),"+f"(c[1]),"+f"(c[2]),"+f"(c[3])
        : "r"(a0),"r"(a1),"r"(a2),"r"(a3),"r"(b0),"r"(b1));
}
__device__ __forceinline__ void mma_bf16(float c[4], uint32_t a0, uint32_t a1, uint32_t a2,
                                         uint32_t a3, uint32_t b0, uint32_t b1){
    asm volatile("mma.sync.aligned.m16n8k16.row.col.f32.bf16.bf16.f32 "
        "{%0,%1,%2,%3},{%4,%5,%6,%7},{%8,%9},{%0,%1,%2,%3};\n"
        : "+f"(c[0]),"+f"(c[1]),"+f"(c[2]),"+f"(c[3])
        : "r"(a0),"r"(a1),"r"(a2),"r"(a3),"r"(b0),"r"(b1));
}
__device__ __forceinline__ void cp16(uint32_t s, const void* g){
    asm volatile("cp.async.cg.shared.global [%0], [%1], 16;" :: "r"(s), "l"(g));
}
__device__ __forceinline__ uint32_t smem_u32(const void* p){
    uint32_t a;
    asm("{ .reg .u64 t; cvta.to.shared.u64 t, %1; cvt.u32.u64 %0, t; }" : "=r"(a) : "l"(p));
    return a;
}
__device__ __forceinline__ uint32_t lds32(const char* smbase, uint32_t off){
    return *(const uint32_t*)(smbase + off);
}

// -------------------- bf16 GEMM (Round-4 config) --------------------
// C(M,1024) = A(M,1024) @ Wt^T + bias. Tile 128x128, k-tile 64, 3-stage cp.async,
// 8 warps (4m x 2n), warp tile 32x64. smem 96KB, 2 CTAs/SM.
// EPI: 0 = fp32 store, 1 = shifted residual-add into out, 2 = bf16 store.
#define NS 16
#define G_SMEM (3*32768)

template<int EPI>
__global__ void __launch_bounds__(256, 2) gemm_bf16_kernel(
    const __nv_bfloat16* __restrict__ A, const __nv_bfloat16* __restrict__ Bt,
    const float* __restrict__ bias, void* __restrict__ CoutV,
    const float* __restrict__ resid)
{
    extern __shared__ char smc[];
    const uint32_t smem_base = smem_u32(smc);
    const int tid = threadIdx.x;
    const int wid = tid >> 5, lane = tid & 31;
    const int wm = wid & 3, wn = wid >> 2;
    const int quad = lane >> 2, qt = lane & 3;
    const int bm = blockIdx.y, bn = blockIdx.x;
    const long arow0 = (long)bm * 128;
    const long brow0 = (long)bn * 128;

    float acc[2][8][4] = {};

    auto load_stage = [&](int kt, int s){
        const uint32_t sb = smem_base + s*32768;
#pragma unroll
        for (int i = 0; i < 4; i++){
            const int idx = i*256 + tid;
            const int r = idx >> 3, c = idx & 7;
            const int sc = c ^ (r & 7);
            cp16(sb + r*128 + sc*16,          &A [(arow0 + r)*1024 + kt*64 + c*8]);
            cp16(sb + 16384 + r*128 + sc*16,  &Bt[(brow0 + r)*1024 + kt*64 + c*8]);
        }
    };

    load_stage(0, 0); asm volatile("cp.async.commit_group;" ::: "memory");
    load_stage(1, 1); asm volatile("cp.async.commit_group;" ::: "memory");

    for (int kt = 0; kt < NS; ++kt){
        if (kt < NS-1) asm volatile("cp.async.wait_group 1;" ::: "memory");
        else           asm volatile("cp.async.wait_group 0;" ::: "memory");
        __syncthreads();
        if (kt + 2 < NS){
            load_stage(kt + 2, (kt + 2) % 3);
            asm volatile("cp.async.commit_group;" ::: "memory");
        }
        const char* Asm = smc + (kt % 3)*32768;
        const char* Bsm = Asm + 16384;

#pragma unroll
        for (int g = 0; g < 4; ++g){
            uint32_t a[2][4];
#pragma unroll
            for (int mi = 0; mi < 2; ++mi){
                const int r0 = wm*32 + mi*16 + quad;
                const int r1 = r0 + 8;
                a[mi][0] = lds32(Asm, r0*128 + ((2*g  ) ^ (r0 & 7))*16 + qt*4);
                a[mi][1] = lds32(Asm, r1*128 + ((2*g  ) ^ (r1 & 7))*16 + qt*4);
                a[mi][2] = lds32(Asm, r0*128 + ((2*g+1) ^ (r0 & 7))*16 + qt*4);
                a[mi][3] = lds32(Asm, r1*128 + ((2*g+1) ^ (r1 & 7))*16 + qt*4);
            }
            uint32_t bfr[8][2];
#pragma unroll
            for (int ni = 0; ni < 8; ++ni){
                const int n = wn*64 + ni*8 + quad;
                bfr[ni][0] = lds32(Bsm, n*128 + ((2*g  ) ^ (n & 7))*16 + qt*4);
                bfr[ni][1] = lds32(Bsm, n*128 + ((2*g+1) ^ (n & 7))*16 + qt*4);
            }
#pragma unroll
            for (int mi = 0; mi < 2; ++mi)
#pragma unroll
                for (int ni = 0; ni < 8; ++ni)
                    mma_bf16(acc[mi][ni], a[mi][0], a[mi][1], a[mi][2], a[mi][3],
                             bfr[ni][0], bfr[ni][1]);
        }
        __syncthreads();
    }

    // epilogue
    float* Cf = (float*)CoutV;
    __nv_bfloat16* Cb = (__nv_bfloat16*)CoutV;
#pragma unroll
    for (int mi = 0; mi < 2; ++mi){
#pragma unroll
        for (int ni = 0; ni < 8; ++ni){
            const int gr0 = bm*128 + wm*32 + mi*16 + quad;
            const int gc  = bn*128 + wn*64 + ni*8 + qt*2;
            const float b0 = bias[gc], b1 = bias[gc+1];
#pragma unroll
            for (int half = 0; half < 2; ++half){
                const int gr = gr0 + half*8;
                const float v0 = acc[mi][ni][half*2+0] + b0;
                const float v1 = acc[mi][ni][half*2+1] + b1;
                if (EPI == 0){
                    Cf[(long)gr*1024 + gc]     = v0;
                    Cf[(long)gr*1024 + gc + 1] = v1;
                } else if (EPI == 1){
                    const int b = gr >> 11, r = gr & 2047;
                    if (r < VALID_ROWS){
                        const long o = ((long)b*PS + r + (PCHUNK-1))*PD + gc;
                        Cf[o]   = v0 + resid[o];
                        Cf[o+1] = v1 + resid[o+1];
                    }
                } else {
                    *(__nv_bfloat162*)&Cb[(long)gr*1024 + gc] =
                        __float22bfloat162_rn(make_float2(v0, v1));
                }
            }
        }
    }
}

// -------------------- e -> bf16 --------------------
__global__ void __launch_bounds__(256) convert_e_kernel(const float* __restrict__ e,
                                                        __nv_bfloat16* __restrict__ E){
    const long i4 = ((long)blockIdx.x*256 + threadIdx.x) * 4;
    float4 v = *(const float4*)&e[i4];
    *(__nv_bfloat162*)&E[i4]     = __float22bfloat162_rn(make_float2(v.x, v.y));
    *(__nv_bfloat162*)&E[i4 + 2] = __float22bfloat162_rn(make_float2(v.z, v.w));
}

// -------------------- 4 weight transposes in one launch -> bf16 [N][K] --------------------
__global__ void __launch_bounds__(256) transpose4_kernel(
    const float* __restrict__ s0, const float* __restrict__ s1,
    const float* __restrict__ s2, const float* __restrict__ s3,
    __nv_bfloat16* __restrict__ dstBase)
{
    __shared__ float t[32][33];
    const int z = blockIdx.z;
    const float* src = (z==0) ? s0 : (z==1) ? s1 : (z==2) ? s2 : s3;
    __nv_bfloat16* dst = dstBase + (long)z*PD*PD;
    const int tx = threadIdx.x, ty = threadIdx.y;
    int x = blockIdx.x*32 + tx;
    int y = blockIdx.y*32 + ty;
#pragma unroll
    for (int j=0;j<32;j+=8) t[ty+j][tx] = src[(long)(y+j)*1024 + x];
    __syncthreads();
    x = blockIdx.y*32 + tx;
    y = blockIdx.x*32 + ty;
#pragma unroll
    for (int j=0;j<32;j+=8)
        dst[(long)(y+j)*1024 + x] = __float2bfloat16_rn(t[tx][ty+j]);
}

// -------------------- LayerNorm (+pad), bf16 output --------------------
__global__ void __launch_bounds__(256) ln_kernel(
    const float* __restrict__ h, const float* __restrict__ gamma,
    const float* __restrict__ beta, __nv_bfloat16* __restrict__ X)
{
    const int row = blockIdx.x;
    const int b = row >> 11, r = row & 2047;
    const int tid = threadIdx.x;
    __nv_bfloat16* xo = X + (long)row * PD;
    if (r >= VALID_ROWS){
        __nv_bfloat162 z = __float22bfloat162_rn(make_float2(0.f,0.f));
        *(__nv_bfloat162*)&xo[tid*4]   = z;
        *(__nv_bfloat162*)&xo[tid*4+2] = z;
        return;
    }
    const float* hp = h + ((long)b*PS + r + (PCHUNK-1)) * PD;
    float4 v = *(const float4*)&hp[tid*4];
    float s  = v.x + v.y + v.z + v.w;
    float sq = v.x*v.x + v.y*v.y + v.z*v.z + v.w*v.w;
#pragma unroll
    for (int o=16;o;o>>=1){
        s  += __shfl_down_sync(0xffffffffu, s,  o);
        sq += __shfl_down_sync(0xffffffffu, sq, o);
    }
    __shared__ float rs_[8], rq_[8];
    __shared__ float mu_s, rstd_s;
    const int wid = tid>>5, lane = tid&31;
    if (!lane){ rs_[wid]=s; rq_[wid]=sq; }
    __syncthreads();
    if (tid==0){
        float ts=0.f, tq=0.f;
#pragma unroll
        for (int i=0;i<8;i++){ ts+=rs_[i]; tq+=rq_[i]; }
        float mu = ts * (1.0f/PD);
        float var = tq * (1.0f/PD) - mu*mu;
        mu_s = mu; rstd_s = rsqrtf(var + 1e-5f);
    }
    __syncthreads();
    const float mu = mu_s, rstd = rstd_s;
    float4 g  = *(const float4*)&gamma[tid*4];
    float4 be = *(const float4*)&beta[tid*4];
    float2 p0 = make_float2((v.x-mu)*rstd*g.x + be.x, (v.y-mu)*rstd*g.y + be.y);
    float2 p1 = make_float2((v.z-mu)*rstd*g.z + be.z, (v.w-mu)*rstd*g.w + be.w);
    *(__nv_bfloat162*)&xo[tid*4]   = __float22bfloat162_rn(p0);
    *(__nv_bfloat162*)&xo[tid*4+2] = __float22bfloat162_rn(p1);
}

// -------------------- attention (per b,c,h) --------------------
// Q fp32; K/V bf16 (expanded to fp32 in smem; bf16->tf32 exact).
#define ATT_SMEM ((64*72*2 + 64*260) * 4)

__global__ void __launch_bounds__(128) attn_kernel(
    const float* __restrict__ Q, const __nv_bfloat16* __restrict__ Kb,
    const __nv_bfloat16* __restrict__ Vb, __nv_bfloat16* __restrict__ AO)
{
    extern __shared__ float sm[];
    float* Qs  = sm;
    float* KVs = sm + 64*72;
    float* Ss  = sm + 2*64*72;
    const int hh = blockIdx.x, c = blockIdx.y, b = blockIdx.z;
    const int tid = threadIdx.x, w = tid>>5, lane = tid&31;
    const int quad = lane>>2, qt = lane&3;
    const long qbase  = ((long)((b*PC + c)*PCHUNK))*PD + hh*PDK;
    const long kvbase = ((long)((b*PC + c)*PNL ))*PD + hh*PDK;

    // load Q (64x64 fp32)
#pragma unroll
    for (int it=0; it<8; it++){
        int idx = tid + it*128;
        int r = idx>>4, c4 = idx&15;
        *(float4*)&Qs[r*72 + c4*4] = *(const float4*)&Q[qbase + (long)r*1024 + c4*4];
    }

    // bf16 tile loader: 64x64 bf16 -> fp32 smem
    auto load_kv = [&](const __nv_bfloat16* src, int jt){
#pragma unroll
        for (int it=0; it<4; it++){
            int idx = tid + it*128;
            int r = idx>>3, c8 = idx&7;
            float4 raw = *(const float4*)&src[kvbase + (long)(jt*64 + r)*1024 + c8*8];
            const __nv_bfloat162* p = (const __nv_bfloat162*)&raw;
            float2 f0 = __bfloat1622float2(p[0]);
            float2 f1 = __bfloat1622float2(p[1]);
            float2 f2 = __bfloat1622float2(p[2]);
            float2 f3 = __bfloat1622float2(p[3]);
            float* d = &KVs[r*72 + c8*8];
            d[0]=f0.x; d[1]=f0.y; d[2]=f1.x; d[3]=f1.y;
            d[4]=f2.x; d[5]=f2.y; d[6]=f3.x; d[7]=f3.y;
        }
    };

    // ---- S = q k^T ----
    for (int jt=0; jt<4; jt++){
        __syncthreads();
        load_kv(Kb, jt);
        __syncthreads();
        float acc[8][4] = {};
#pragma unroll
        for (int kk=0; kk<64; kk+=8){
            uint32_t af[4];
            const int ib = w*16;
            af[0]=f2tf32(Qs[(ib+quad  )*72 + kk+qt  ]);
            af[1]=f2tf32(Qs[(ib+quad+8)*72 + kk+qt  ]);
            af[2]=f2tf32(Qs[(ib+quad  )*72 + kk+qt+4]);
            af[3]=f2tf32(Qs[(ib+quad+8)*72 + kk+qt+4]);
#pragma unroll
            for (int ni=0; ni<8; ni++){
                uint32_t b0=f2tf32(KVs[(ni*8+quad)*72 + kk+qt  ]);
                uint32_t b1=f2tf32(KVs[(ni*8+quad)*72 + kk+qt+4]);
                mma_tf32(acc[ni], af[0],af[1],af[2],af[3], b0,b1);
            }
        }
#pragma unroll
        for (int ni=0; ni<8; ni++){
            const int i0 = w*16 + quad;
            const int j0 = jt*64 + ni*8 + qt*2;
            Ss[i0*260 + j0]       = acc[ni][0]*PSCALE;
            Ss[i0*260 + j0+1]     = acc[ni][1]*PSCALE;
            Ss[(i0+8)*260 + j0]   = acc[ni][2]*PSCALE;
            Ss[(i0+8)*260 + j0+1] = acc[ni][3]*PSCALE;
        }
    }
    __syncthreads();

    // ---- softmax: warp-per-row (each warp does 16 rows; lane covers 8 cols) ----
    for (int rr = 0; rr < 16; ++rr){
        const int row = w*16 + rr;
        float* rp = &Ss[row*260];
        float v[8];
        float m = -1e30f;
#pragma unroll
        for (int j=0;j<8;j++){ v[j] = rp[lane + j*32]; m = fmaxf(m, v[j]); }
#pragma unroll
        for (int o=16;o;o>>=1) m = fmaxf(m, __shfl_xor_sync(0xffffffffu, m, o));
        float ssum = 0.f;
#pragma unroll
        for (int j=0;j<8;j++){ v[j] = __expf(v[j]-m); ssum += v[j]; }
#pragma unroll
        for (int o=16;o;o>>=1) ssum += __shfl_xor_sync(0xffffffffu, ssum, o);
        const float inv = 1.0f/ssum;
#pragma unroll
        for (int j=0;j<8;j++) rp[lane + j*32] = v[j]*inv;
    }

    // ---- O = P @ V ----
    float accO[8][4] = {};
    for (int jt=0; jt<4; jt++){
        __syncthreads();
        load_kv(Vb, jt);
        __syncthreads();
#pragma unroll
        for (int kk=0; kk<64; kk+=8){
            uint32_t af[4];
            const int ib = w*16;
            const int jcol = jt*64 + kk;
            af[0]=f2tf32(Ss[(ib+quad  )*260 + jcol+qt  ]);
            af[1]=f2tf32(Ss[(ib+quad+8)*260 + jcol+qt  ]);
            af[2]=f2tf32(Ss[(ib+quad  )*260 + jcol+qt+4]);
            af[3]=f2tf32(Ss[(ib+quad+8)*260 + jcol+qt+4]);
#pragma unroll
            for (int ni=0; ni<8; ni++){
                uint32_t b0=f2tf32(KVs[(kk+qt  )*72 + ni*8+quad]);
                uint32_t b1=f2tf32(KVs[(kk+qt+4)*72 + ni*8+quad]);
                mma_tf32(accO[ni], af[0],af[1],af[2],af[3], b0,b1);
            }
        }
    }
#pragma unroll
    for (int ni=0; ni<8; ni++){
        const int i0 = w*16 + quad;
        const int d0 = ni*8 + qt*2;
        *(__nv_bfloat162*)&AO[qbase + (long)i0*1024 + d0] =
            __float22bfloat162_rn(make_float2(accO[ni][0], accO[ni][1]));
        *(__nv_bfloat162*)&AO[qbase + (long)(i0+8)*1024 + d0] =
            __float22bfloat162_rn(make_float2(accO[ni][2], accO[ni][3]));
    }
}

// -------------------- copy first 63 rows --------------------
__global__ void copy_head_kernel(const float* __restrict__ h, float* __restrict__ out){
    const int idx = blockIdx.x*256 + threadIdx.x;
    if (idx >= PB*(PCHUNK-1)*(PD/4)) return;
    const int b = idx / ((PCHUNK-1)*(PD/4));
    const int rem = idx % ((PCHUNK-1)*(PD/4));
    const int s = rem >> 8, c4 = rem & 255;
    const long o = ((long)b*PS + s)*PD + c4*4;
    *(float4*)&out[o] = *(const float4*)&h[o];
}

// -------------------- launch --------------------
extern "C" void kernel_launch(void* const* d_in, const int* in_sizes, int n_in,
                              void* d_out, int out_size)
{
    const float* h     = (const float*)d_in[0];
    const float* e     = (const float*)d_in[1];
    const float* Wq    = (const float*)d_in[2];
    const float* bq    = (const float*)d_in[3];
    const float* Wk    = (const float*)d_in[4];
    const float* bk    = (const float*)d_in[5];
    const float* Wv    = (const float*)d_in[6];
    const float* bv    = (const float*)d_in[7];
    const float* Wo    = (const float*)d_in[8];
    const float* bo    = (const float*)d_in[9];
    const float* gamma = (const float*)d_in[10];
    const float* beta  = (const float*)d_in[11];
    float* out = (float*)d_out;

    void *pX,*pE,*pQ,*pK,*pV,*pA,*pW;
    cudaGetSymbolAddress(&pX, g_X);
    cudaGetSymbolAddress(&pE, g_E);
    cudaGetSymbolAddress(&pQ, g_Q);
    cudaGetSymbolAddress(&pK, g_K);
    cudaGetSymbolAddress(&pV, g_V);
    cudaGetSymbolAddress(&pA, g_AO);
    cudaGetSymbolAddress(&pW, g_Wt);
    __nv_bfloat16* Wt = (__nv_bfloat16*)pW;

    cudaFuncSetAttribute(gemm_bf16_kernel<0>, cudaFuncAttributeMaxDynamicSharedMemorySize, G_SMEM);
    cudaFuncSetAttribute(gemm_bf16_kernel<1>, cudaFuncAttributeMaxDynamicSharedMemorySize, G_SMEM);
    cudaFuncSetAttribute(gemm_bf16_kernel<2>, cudaFuncAttributeMaxDynamicSharedMemorySize, G_SMEM);
    cudaFuncSetAttribute(attn_kernel,         cudaFuncAttributeMaxDynamicSharedMemorySize, ATT_SMEM);

    // 0) operand prep
    transpose4_kernel<<<dim3(32,32,4), dim3(32,8)>>>(Wq, Wk, Wv, Wo, Wt);
    convert_e_kernel<<<PB*PC*PNL*PD/1024, 256>>>(e, (__nv_bfloat16*)pE);
    ln_kernel<<<PB*PS, 256>>>(h, gamma, beta, (__nv_bfloat16*)pX);
    // 1) projections: Q fp32 out; K/V bf16 out
    gemm_bf16_kernel<0><<<dim3(8,64),  256, G_SMEM>>>((const __nv_bfloat16*)pX, Wt + 0*PD*PD, bq, pQ, nullptr);
    gemm_bf16_kernel<2><<<dim3(8,256), 256, G_SMEM>>>((const __nv_bfloat16*)pE, Wt + 1*PD*PD, bk, pK, nullptr);
    gemm_bf16_kernel<2><<<dim3(8,256), 256, G_SMEM>>>((const __nv_bfloat16*)pE, Wt + 2*PD*PD, bv, pV, nullptr);
    // 2) attention
    attn_kernel<<<dim3(PH, PC, PB), 128, ATT_SMEM>>>((const float*)pQ, (const __nv_bfloat16*)pK,
                                                     (const __nv_bfloat16*)pV, (__nv_bfloat16*)pA);
    // 3) output projection + shifted residual
    gemm_bf16_kernel<1><<<dim3(8,64),  256, G_SMEM>>>((const __nv_bfloat16*)pA, Wt + 3*PD*PD, bo, out, h);
    // 4) head rows
    copy_head_kernel<<<(PB*(PCHUNK-1)*(PD/4) + 255)/256, 256>>>(h, out);
}

// round 8
// speedup vs baseline: 1.0748x; 1.0084x over previous
#include <cuda_runtime.h>
#include <cuda_bf16.h>
#include <cstdint>

// Problem constants
#define PB 4
#define PS 2048
#define PD 1024
#define PC 32
#define PNL 256
#define PH 16
#define PDK 64
#define PCHUNK 64
#define PSCALE 0.125f
#define VALID_ROWS 1985

// -------------------- scratch --------------------
__device__ __nv_bfloat16 g_X [PB*PS*PD];
__device__ __nv_bfloat16 g_E [PB*PC*PNL*PD];
__device__ __nv_bfloat16 g_AO[PB*PS*PD];
__device__ __nv_bfloat16 g_Wt[4*PD*PD];
__device__ float         g_Q [PB*PS*PD];
__device__ __nv_bfloat16 g_K [PB*PC*PNL*PD];
__device__ __nv_bfloat16 g_V [PB*PC*PNL*PD];

// -------------------- helpers --------------------
__device__ __forceinline__ uint32_t f2tf32(float f){
    uint32_t r; asm("cvt.rna.tf32.f32 %0, %1;" : "=r"(r) : "f"(f)); return r;
}
__device__ __forceinline__ void mma_tf32(float c[4], uint32_t a0, uint32_t a1, uint32_t a2,
                                         uint32_t a3, uint32_t b0, uint32_t b1){
    asm volatile("mma.sync.aligned.m16n8k8.row.col.f32.tf32.tf32.f32 "
        "{%0,%1,%2,%3},{%4,%5,%6,%7},{%8,%9},{%0,%1,%2,%3};\n"
        : "+f"(c[0]),"+f"(c[1]),"+f"(c[2]),"+f"(c[3])
        : "r"(a0),"r"(a1),"r"(a2),"r"(a3),"r"(b0),"r"(b1));
}
__device__ __forceinline__ void mma_bf16(float c[4], uint32_t a0, uint32_t a1, uint32_t a2,
                                         uint32_t a3, uint32_t b0, uint32_t b1){
    asm volatile("mma.sync.aligned.m16n8k16.row.col.f32.bf16.bf16.f32 "
        "{%0,%1,%2,%3},{%4,%5,%6,%7},{%8,%9},{%0,%1,%2,%3};\n"
        : "+f"(c[0]),"+f"(c[1]),"+f"(c[2]),"+f"(c[3])
        : "r"(a0),"r"(a1),"r"(a2),"r"(a3),"r"(b0),"r"(b1));
}
__device__ __forceinline__ void cp16(uint32_t s, const void* g){
    asm volatile("cp.async.cg.shared.global [%0], [%1], 16;" :: "r"(s), "l"(g));
}
__device__ __forceinline__ uint32_t smem_u32(const void* p){
    uint32_t a;
    asm("{ .reg .u64 t; cvta.to.shared.u64 t, %1; cvt.u32.u64 %0, t; }" : "=r"(a) : "l"(p));
    return a;
}
__device__ __forceinline__ uint32_t lds32(const char* smbase, uint32_t off){
    return *(const uint32_t*)(smbase + off);
}

// ==================== merged QKV GEMM ====================
// grid (8, 576): y<64 -> Q (fp32 out), y in [64,320) -> K (bf16 out), [320,576) -> V.
// GEMM core identical to Round-7: tile 128x128, k-tile 64, 3-stage cp.async, 2 CTAs/SM.
#define NS 16
#define G_SMEM (3*32768)

__global__ void __launch_bounds__(256, 2) qkv_gemm_kernel(
    const __nv_bfloat16* __restrict__ X, const __nv_bfloat16* __restrict__ E,
    const __nv_bfloat16* __restrict__ Wt,
    const float* __restrict__ bq, const float* __restrict__ bk, const float* __restrict__ bv,
    float* __restrict__ Qout, __nv_bfloat16* __restrict__ Kout, __nv_bfloat16* __restrict__ Vout)
{
    extern __shared__ char smc[];
    const uint32_t smem_base = smem_u32(smc);
    const int tid = threadIdx.x;
    const int wid = tid >> 5, lane = tid & 31;
    const int wm = wid & 3, wn = wid >> 2;
    const int quad = lane >> 2, qt = lane & 3;
    const int by = blockIdx.y, bn = blockIdx.x;

    const __nv_bfloat16* A; const __nv_bfloat16* Bt; const float* bias;
    int bm, mode;   // mode 0: fp32 store, 1: bf16 store
    float* Cf = nullptr; __nv_bfloat16* Cb = nullptr;
    if (by < 64){        A = X; Bt = Wt;           bias = bq; bm = by;       mode = 0; Cf = Qout; }
    else if (by < 320){  A = E; Bt = Wt + PD*PD;   bias = bk; bm = by - 64;  mode = 1; Cb = Kout; }
    else {               A = E; Bt = Wt + 2*PD*PD; bias = bv; bm = by - 320; mode = 1; Cb = Vout; }

    const long arow0 = (long)bm * 128;
    const long brow0 = (long)bn * 128;

    float acc[2][8][4] = {};

    auto load_stage = [&](int kt, int s){
        const uint32_t sb = smem_base + s*32768;
#pragma unroll
        for (int i = 0; i < 4; i++){
            const int idx = i*256 + tid;
            const int r = idx >> 3, c = idx & 7;
            const int sc = c ^ (r & 7);
            cp16(sb + r*128 + sc*16,          &A [(arow0 + r)*1024 + kt*64 + c*8]);
            cp16(sb + 16384 + r*128 + sc*16,  &Bt[(brow0 + r)*1024 + kt*64 + c*8]);
        }
    };

    load_stage(0, 0); asm volatile("cp.async.commit_group;" ::: "memory");
    load_stage(1, 1); asm volatile("cp.async.commit_group;" ::: "memory");

    for (int kt = 0; kt < NS; ++kt){
        if (kt < NS-1) asm volatile("cp.async.wait_group 1;" ::: "memory");
        else           asm volatile("cp.async.wait_group 0;" ::: "memory");
        __syncthreads();
        if (kt + 2 < NS){
            load_stage(kt + 2, (kt + 2) % 3);
            asm volatile("cp.async.commit_group;" ::: "memory");
        }
        const char* Asm = smc + (kt % 3)*32768;
        const char* Bsm = Asm + 16384;

#pragma unroll
        for (int g = 0; g < 4; ++g){
            uint32_t a[2][4];
#pragma unroll
            for (int mi = 0; mi < 2; ++mi){
                const int r0 = wm*32 + mi*16 + quad;
                const int r1 = r0 + 8;
                a[mi][0] = lds32(Asm, r0*128 + ((2*g  ) ^ (r0 & 7))*16 + qt*4);
                a[mi][1] = lds32(Asm, r1*128 + ((2*g  ) ^ (r1 & 7))*16 + qt*4);
                a[mi][2] = lds32(Asm, r0*128 + ((2*g+1) ^ (r0 & 7))*16 + qt*4);
                a[mi][3] = lds32(Asm, r1*128 + ((2*g+1) ^ (r1 & 7))*16 + qt*4);
            }
            uint32_t bfr[8][2];
#pragma unroll
            for (int ni = 0; ni < 8; ++ni){
                const int n = wn*64 + ni*8 + quad;
                bfr[ni][0] = lds32(Bsm, n*128 + ((2*g  ) ^ (n & 7))*16 + qt*4);
                bfr[ni][1] = lds32(Bsm, n*128 + ((2*g+1) ^ (n & 7))*16 + qt*4);
            }
#pragma unroll
            for (int mi = 0; mi < 2; ++mi)
#pragma unroll
                for (int ni = 0; ni < 8; ++ni)
                    mma_bf16(acc[mi][ni], a[mi][0], a[mi][1], a[mi][2], a[mi][3],
                             bfr[ni][0], bfr[ni][1]);
        }
        __syncthreads();
    }

    // epilogue
#pragma unroll
    for (int mi = 0; mi < 2; ++mi){
#pragma unroll
        for (int ni = 0; ni < 8; ++ni){
            const int gr0 = bm*128 + wm*32 + mi*16 + quad;
            const int gc  = bn*128 + wn*64 + ni*8 + qt*2;
            const float b0 = bias[gc], b1 = bias[gc+1];
#pragma unroll
            for (int half = 0; half < 2; ++half){
                const int gr = gr0 + half*8;
                const float v0 = acc[mi][ni][half*2+0] + b0;
                const float v1 = acc[mi][ni][half*2+1] + b1;
                if (mode == 0){
                    Cf[(long)gr*1024 + gc]     = v0;
                    Cf[(long)gr*1024 + gc + 1] = v1;
                } else {
                    *(__nv_bfloat162*)&Cb[(long)gr*1024 + gc] =
                        __float22bfloat162_rn(make_float2(v0, v1));
                }
            }
        }
    }
}

// ==================== O GEMM (shifted residual epilogue) ====================
__global__ void __launch_bounds__(256, 2) o_gemm_kernel(
    const __nv_bfloat16* __restrict__ A, const __nv_bfloat16* __restrict__ Bt,
    const float* __restrict__ bias, float* __restrict__ Cout,
    const float* __restrict__ resid)
{
    extern __shared__ char smc[];
    const uint32_t smem_base = smem_u32(smc);
    const int tid = threadIdx.x;
    const int wid = tid >> 5, lane = tid & 31;
    const int wm = wid & 3, wn = wid >> 2;
    const int quad = lane >> 2, qt = lane & 3;
    const int bm = blockIdx.y, bn = blockIdx.x;
    const long arow0 = (long)bm * 128;
    const long brow0 = (long)bn * 128;

    float acc[2][8][4] = {};

    auto load_stage = [&](int kt, int s){
        const uint32_t sb = smem_base + s*32768;
#pragma unroll
        for (int i = 0; i < 4; i++){
            const int idx = i*256 + tid;
            const int r = idx >> 3, c = idx & 7;
            const int sc = c ^ (r & 7);
            cp16(sb + r*128 + sc*16,          &A [(arow0 + r)*1024 + kt*64 + c*8]);
            cp16(sb + 16384 + r*128 + sc*16,  &Bt[(brow0 + r)*1024 + kt*64 + c*8]);
        }
    };

    load_stage(0, 0); asm volatile("cp.async.commit_group;" ::: "memory");
    load_stage(1, 1); asm volatile("cp.async.commit_group;" ::: "memory");

    for (int kt = 0; kt < NS; ++kt){
        if (kt < NS-1) asm volatile("cp.async.wait_group 1;" ::: "memory");
        else           asm volatile("cp.async.wait_group 0;" ::: "memory");
        __syncthreads();
        if (kt + 2 < NS){
            load_stage(kt + 2, (kt + 2) % 3);
            asm volatile("cp.async.commit_group;" ::: "memory");
        }
        const char* Asm = smc + (kt % 3)*32768;
        const char* Bsm = Asm + 16384;

#pragma unroll
        for (int g = 0; g < 4; ++g){
            uint32_t a[2][4];
#pragma unroll
            for (int mi = 0; mi < 2; ++mi){
                const int r0 = wm*32 + mi*16 + quad;
                const int r1 = r0 + 8;
                a[mi][0] = lds32(Asm, r0*128 + ((2*g  ) ^ (r0 & 7))*16 + qt*4);
                a[mi][1] = lds32(Asm, r1*128 + ((2*g  ) ^ (r1 & 7))*16 + qt*4);
                a[mi][2] = lds32(Asm, r0*128 + ((2*g+1) ^ (r0 & 7))*16 + qt*4);
                a[mi][3] = lds32(Asm, r1*128 + ((2*g+1) ^ (r1 & 7))*16 + qt*4);
            }
            uint32_t bfr[8][2];
#pragma unroll
            for (int ni = 0; ni < 8; ++ni){
                const int n = wn*64 + ni*8 + quad;
                bfr[ni][0] = lds32(Bsm, n*128 + ((2*g  ) ^ (n & 7))*16 + qt*4);
                bfr[ni][1] = lds32(Bsm, n*128 + ((2*g+1) ^ (n & 7))*16 + qt*4);
            }
#pragma unroll
            for (int mi = 0; mi < 2; ++mi)
#pragma unroll
                for (int ni = 0; ni < 8; ++ni)
                    mma_bf16(acc[mi][ni], a[mi][0], a[mi][1], a[mi][2], a[mi][3],
                             bfr[ni][0], bfr[ni][1]);
        }
        __syncthreads();
    }

#pragma unroll
    for (int mi = 0; mi < 2; ++mi){
#pragma unroll
        for (int ni = 0; ni < 8; ++ni){
            const int gr0 = bm*128 + wm*32 + mi*16 + quad;
            const int gc  = bn*128 + wn*64 + ni*8 + qt*2;
            const float b0 = bias[gc], b1 = bias[gc+1];
#pragma unroll
            for (int half = 0; half < 2; ++half){
                const int gr = gr0 + half*8;
                const float v0 = acc[mi][ni][half*2+0] + b0;
                const float v1 = acc[mi][ni][half*2+1] + b1;
                const int b = gr >> 11, r = gr & 2047;
                if (r < VALID_ROWS){
                    const long o = ((long)b*PS + r + (PCHUNK-1))*PD + gc;
                    Cout[o]   = v0 + resid[o];
                    Cout[o+1] = v1 + resid[o+1];
                }
            }
        }
    }
}

// ==================== merged prep kernel ====================
// grid.x partition: [0,4096) transpose4, [4096,36864) convert_e,
// [36864,45056) layernorm, [45056,45308) copy_head. 256 threads each.
#define TR_B 4096
#define CE_B 32768
#define LN_B 8192
#define CH_B 252
#define CH_TOT (PB*(PCHUNK-1)*(PD/4))   // 64512 float4 chunks

__global__ void __launch_bounds__(256) prep_kernel(
    const float* __restrict__ h, const float* __restrict__ e,
    const float* __restrict__ Wq, const float* __restrict__ Wk,
    const float* __restrict__ Wv, const float* __restrict__ Wo,
    const float* __restrict__ gamma, const float* __restrict__ beta,
    __nv_bfloat16* __restrict__ Wt, __nv_bfloat16* __restrict__ E,
    __nv_bfloat16* __restrict__ X, float* __restrict__ out)
{
    __shared__ float t[32][33];
    __shared__ float rs_[8], rq_[8];
    __shared__ float mu_s, rstd_s;
    const int blk = blockIdx.x;
    const int tid = threadIdx.x;

    if (blk < TR_B){
        // ---- weight transpose: dst[n][k] = bf16(src[k][n]) ----
        const int z = blk >> 10, r = blk & 1023;
        const int bx = r & 31, byy = r >> 5;
        const float* src = (z==0) ? Wq : (z==1) ? Wk : (z==2) ? Wv : Wo;
        __nv_bfloat16* dst = Wt + (long)z*PD*PD;
        const int tx = tid & 31, ty = tid >> 5;   // ty 0..7
        int x = bx*32 + tx;
        int y = byy*32 + ty;
#pragma unroll
        for (int j=0;j<32;j+=8) t[ty+j][tx] = src[(long)(y+j)*1024 + x];
        __syncthreads();
        x = byy*32 + tx;
        y = bx*32 + ty;
#pragma unroll
        for (int j=0;j<32;j+=8)
            dst[(long)(y+j)*1024 + x] = __float2bfloat16_rn(t[tx][ty+j]);
        return;
    }
    if (blk < TR_B + CE_B){
        // ---- e -> bf16 ----
        const long i4 = ((long)(blk - TR_B)*256 + tid) * 4;
        float4 v = *(const float4*)&e[i4];
        *(__nv_bfloat162*)&E[i4]     = __float22bfloat162_rn(make_float2(v.x, v.y));
        *(__nv_bfloat162*)&E[i4 + 2] = __float22bfloat162_rn(make_float2(v.z, v.w));
        return;
    }
    if (blk < TR_B + CE_B + LN_B){
        // ---- layernorm (+pad) ----
        const int row = blk - TR_B - CE_B;
        const int b = row >> 11, r = row & 2047;
        __nv_bfloat16* xo = X + (long)row * PD;
        if (r >= VALID_ROWS){
            __nv_bfloat162 z = __float22bfloat162_rn(make_float2(0.f,0.f));
            *(__nv_bfloat162*)&xo[tid*4]   = z;
            *(__nv_bfloat162*)&xo[tid*4+2] = z;
            return;
        }
        const float* hp = h + ((long)b*PS + r + (PCHUNK-1)) * PD;
        float4 v = *(const float4*)&hp[tid*4];
        float s  = v.x + v.y + v.z + v.w;
        float sq = v.x*v.x + v.y*v.y + v.z*v.z + v.w*v.w;
#pragma unroll
        for (int o=16;o;o>>=1){
            s  += __shfl_down_sync(0xffffffffu, s,  o);
            sq += __shfl_down_sync(0xffffffffu, sq, o);
        }
        const int wid = tid>>5, lane = tid&31;
        if (!lane){ rs_[wid]=s; rq_[wid]=sq; }
        __syncthreads();
        if (tid==0){
            float ts=0.f, tq=0.f;
#pragma unroll
            for (int i=0;i<8;i++){ ts+=rs_[i]; tq+=rq_[i]; }
            float mu = ts * (1.0f/PD);
            float var = tq * (1.0f/PD) - mu*mu;
            mu_s = mu; rstd_s = rsqrtf(var + 1e-5f);
        }
        __syncthreads();
        const float mu = mu_s, rstd = rstd_s;
        float4 g  = *(const float4*)&gamma[tid*4];
        float4 be = *(const float4*)&beta[tid*4];
        float2 p0 = make_float2((v.x-mu)*rstd*g.x + be.x, (v.y-mu)*rstd*g.y + be.y);
        float2 p1 = make_float2((v.z-mu)*rstd*g.z + be.z, (v.w-mu)*rstd*g.w + be.w);
        *(__nv_bfloat162*)&xo[tid*4]   = __float22bfloat162_rn(p0);
        *(__nv_bfloat162*)&xo[tid*4+2] = __float22bfloat162_rn(p1);
        return;
    }
    // ---- copy first 63 rows of residual per batch ----
    {
        const int idx = (blk - TR_B - CE_B - LN_B)*256 + tid;
        if (idx >= CH_TOT) return;
        const int b = idx / ((PCHUNK-1)*(PD/4));
        const int rem = idx % ((PCHUNK-1)*(PD/4));
        const int s = rem >> 8, c4 = rem & 255;
        const long o = ((long)b*PS + s)*PD + c4*4;
        *(float4*)&out[o] = *(const float4*)&h[o];
    }
}

// ==================== attention (unchanged from Round 7) ====================
#define ATT_SMEM ((64*72*2 + 64*260) * 4)

__global__ void __launch_bounds__(128) attn_kernel(
    const float* __restrict__ Q, const __nv_bfloat16* __restrict__ Kb,
    const __nv_bfloat16* __restrict__ Vb, __nv_bfloat16* __restrict__ AO)
{
    extern __shared__ float sm[];
    float* Qs  = sm;
    float* KVs = sm + 64*72;
    float* Ss  = sm + 2*64*72;
    const int hh = blockIdx.x, c = blockIdx.y, b = blockIdx.z;
    const int tid = threadIdx.x, w = tid>>5, lane = tid&31;
    const int quad = lane>>2, qt = lane&3;
    const long qbase  = ((long)((b*PC + c)*PCHUNK))*PD + hh*PDK;
    const long kvbase = ((long)((b*PC + c)*PNL ))*PD + hh*PDK;

#pragma unroll
    for (int it=0; it<8; it++){
        int idx = tid + it*128;
        int r = idx>>4, c4 = idx&15;
        *(float4*)&Qs[r*72 + c4*4] = *(const float4*)&Q[qbase + (long)r*1024 + c4*4];
    }

    auto load_kv = [&](const __nv_bfloat16* src, int jt){
#pragma unroll
        for (int it=0; it<4; it++){
            int idx = tid + it*128;
            int r = idx>>3, c8 = idx&7;
            float4 raw = *(const float4*)&src[kvbase + (long)(jt*64 + r)*1024 + c8*8];
            const __nv_bfloat162* p = (const __nv_bfloat162*)&raw;
            float2 f0 = __bfloat1622float2(p[0]);
            float2 f1 = __bfloat1622float2(p[1]);
            float2 f2 = __bfloat1622float2(p[2]);
            float2 f3 = __bfloat1622float2(p[3]);
            float* d = &KVs[r*72 + c8*8];
            d[0]=f0.x; d[1]=f0.y; d[2]=f1.x; d[3]=f1.y;
            d[4]=f2.x; d[5]=f2.y; d[6]=f3.x; d[7]=f3.y;
        }
    };

    for (int jt=0; jt<4; jt++){
        __syncthreads();
        load_kv(Kb, jt);
        __syncthreads();
        float acc[8][4] = {};
#pragma unroll
        for (int kk=0; kk<64; kk+=8){
            uint32_t af[4];
            const int ib = w*16;
            af[0]=f2tf32(Qs[(ib+quad  )*72 + kk+qt  ]);
            af[1]=f2tf32(Qs[(ib+quad+8)*72 + kk+qt  ]);
            af[2]=f2tf32(Qs[(ib+quad  )*72 + kk+qt+4]);
            af[3]=f2tf32(Qs[(ib+quad+8)*72 + kk+qt+4]);
#pragma unroll
            for (int ni=0; ni<8; ni++){
                uint32_t b0=f2tf32(KVs[(ni*8+quad)*72 + kk+qt  ]);
                uint32_t b1=f2tf32(KVs[(ni*8+quad)*72 + kk+qt+4]);
                mma_tf32(acc[ni], af[0],af[1],af[2],af[3], b0,b1);
            }
        }
#pragma unroll
        for (int ni=0; ni<8; ni++){
            const int i0 = w*16 + quad;
            const int j0 = jt*64 + ni*8 + qt*2;
            Ss[i0*260 + j0]       = acc[ni][0]*PSCALE;
            Ss[i0*260 + j0+1]     = acc[ni][1]*PSCALE;
            Ss[(i0+8)*260 + j0]   = acc[ni][2]*PSCALE;
            Ss[(i0+8)*260 + j0+1] = acc[ni][3]*PSCALE;
        }
    }
    __syncthreads();

    for (int rr = 0; rr < 16; ++rr){
        const int row = w*16 + rr;
        float* rp = &Ss[row*260];
        float v[8];
        float m = -1e30f;
#pragma unroll
        for (int j=0;j<8;j++){ v[j] = rp[lane + j*32]; m = fmaxf(m, v[j]); }
#pragma unroll
        for (int o=16;o;o>>=1) m = fmaxf(m, __shfl_xor_sync(0xffffffffu, m, o));
        float ssum = 0.f;
#pragma unroll
        for (int j=0;j<8;j++){ v[j] = __expf(v[j]-m); ssum += v[j]; }
#pragma unroll
        for (int o=16;o;o>>=1) ssum += __shfl_xor_sync(0xffffffffu, ssum, o);
        const float inv = 1.0f/ssum;
#pragma unroll
        for (int j=0;j<8;j++) rp[lane + j*32] = v[j]*inv;
    }

    float accO[8][4] = {};
    for (int jt=0; jt<4; jt++){
        __syncthreads();
        load_kv(Vb, jt);
        __syncthreads();
#pragma unroll
        for (int kk=0; kk<64; kk+=8){
            uint32_t af[4];
            const int ib = w*16;
            const int jcol = jt*64 + kk;
            af[0]=f2tf32(Ss[(ib+quad  )*260 + jcol+qt  ]);
            af[1]=f2tf32(Ss[(ib+quad+8)*260 + jcol+qt  ]);
            af[2]=f2tf32(Ss[(ib+quad  )*260 + jcol+qt+4]);
            af[3]=f2tf32(Ss[(ib+quad+8)*260 + jcol+qt+4]);
#pragma unroll
            for (int ni=0; ni<8; ni++){
                uint32_t b0=f2tf32(KVs[(kk+qt  )*72 + ni*8+quad]);
                uint32_t b1=f2tf32(KVs[(kk+qt+4)*72 + ni*8+quad]);
                mma_tf32(accO[ni], af[0],af[1],af[2],af[3], b0,b1);
            }
        }
    }
#pragma unroll
    for (int ni=0; ni<8; ni++){
        const int i0 = w*16 + quad;
        const int d0 = ni*8 + qt*2;
        *(__nv_bfloat162*)&AO[qbase + (long)i0*1024 + d0] =
            __float22bfloat162_rn(make_float2(accO[ni][0], accO[ni][1]));
        *(__nv_bfloat162*)&AO[qbase + (long)(i0+8)*1024 + d0] =
            __float22bfloat162_rn(make_float2(accO[ni][2], accO[ni][3]));
    }
}

// -------------------- launch --------------------
extern "C" void kernel_launch(void* const* d_in, const int* in_sizes, int n_in,
                              void* d_out, int out_size)
{
    const float* h     = (const float*)d_in[0];
    const float* e     = (const float*)d_in[1];
    const float* Wq    = (const float*)d_in[2];
    const float* bq    = (const float*)d_in[3];
    const float* Wk    = (const float*)d_in[4];
    const float* bk    = (const float*)d_in[5];
    const float* Wv    = (const float*)d_in[6];
    const float* bv    = (const float*)d_in[7];
    const float* Wo    = (const float*)d_in[8];
    const float* bo    = (const float*)d_in[9];
    const float* gamma = (const float*)d_in[10];
    const float* beta  = (const float*)d_in[11];
    float* out = (float*)d_out;

    void *pX,*pE,*pQ,*pK,*pV,*pA,*pW;
    cudaGetSymbolAddress(&pX, g_X);
    cudaGetSymbolAddress(&pE, g_E);
    cudaGetSymbolAddress(&pQ, g_Q);
    cudaGetSymbolAddress(&pK, g_K);
    cudaGetSymbolAddress(&pV, g_V);
    cudaGetSymbolAddress(&pA, g_AO);
    cudaGetSymbolAddress(&pW, g_Wt);
    __nv_bfloat16* Wt = (__nv_bfloat16*)pW;

    cudaFuncSetAttribute(qkv_gemm_kernel, cudaFuncAttributeMaxDynamicSharedMemorySize, G_SMEM);
    cudaFuncSetAttribute(o_gemm_kernel,   cudaFuncAttributeMaxDynamicSharedMemorySize, G_SMEM);
    cudaFuncSetAttribute(attn_kernel,     cudaFuncAttributeMaxDynamicSharedMemorySize, ATT_SMEM);

    // 1) prep: transpose weights + convert e + layernorm + head-row copy
    prep_kernel<<<TR_B + CE_B + LN_B + CH_B, 256>>>(
        h, e, Wq, Wk, Wv, Wo, gamma, beta,
        Wt, (__nv_bfloat16*)pE, (__nv_bfloat16*)pX, out);
    // 2) Q + K + V projections in one launch
    qkv_gemm_kernel<<<dim3(8, 576), 256, G_SMEM>>>(
        (const __nv_bfloat16*)pX, (const __nv_bfloat16*)pE, Wt,
        bq, bk, bv, (float*)pQ, (__nv_bfloat16*)pK, (__nv_bfloat16*)pV);
    // 3) attention
    attn_kernel<<<dim3(PH, PC, PB), 128, ATT_SMEM>>>((const float*)pQ, (const __nv_bfloat16*)pK,
                                                     (const __nv_bfloat16*)pV, (__nv_bfloat16*)pA);
    // 4) output projection + shifted residual
    o_gemm_kernel<<<dim3(8,64), 256, G_SMEM>>>((const __nv_bfloat16*)pA, Wt + 3*PD*PD, bo, out, h);
}